// round 2
// baseline (speedup 1.0000x reference)
#include <cuda_runtime.h>

// ============================================================================
// SphericalHarmonicsGaussianKernels
//   patches: (8, 2048, 32, 3) fp32   -> d_in[0]
//   Y:       (16, 20) fp32           -> d_in[1]
//   out:     (8, 2048, 32, 16, 4) fp32
//
// Plan (4 launches, all plain kernels — nothing else in the graph):
//   k_zero     : zero the 8x16 accumulator
//   k_reduce   : per (b,v) warp computes sum_p of (shn_s * sh_m)^2 grouped by
//                degree, sqrt per v, accumulate per batch (smem + global atomics)
//   k_finalize : ninv[b][l][s] = 1 / max(acc/2048, 1e-8)
//   k_out      : recompute point math, write sh[m]*shn[s]*ninv (134 MB stream)
// ============================================================================

__device__ float g_acc[128];      // [b][l*4+s]
__device__ float g_ninv[128];     // [b][l*4+s]

// ---------------------------------------------------------------------------
// Per-point evaluation: sh[16] (Y . monomials) and shn[4] (normalized, masked
// gaussian shells). sY = Y in shared memory, row-major [16][20].
// Monomial order = sorted lexicographic (i,j,k), i = x-exponent:
//  0:1  1:z  2:z2  3:z3  4:y  5:yz  6:yz2  7:y2  8:y2z  9:y3
// 10:x 11:xz 12:xz2 13:xy 14:xyz 15:xy2 16:x2 17:x2z 18:x2y 19:x3
// ---------------------------------------------------------------------------
__device__ __forceinline__ void point_eval(const float* __restrict__ sY,
                                           float x, float y, float z,
                                           float sh[16], float shn[4]) {
    float r2   = fmaf(x, x, fmaf(y, y, z * z));
    float dist = sqrtf(r2);
    float inv  = 1.0f / fmaxf(dist, 1e-6f);
    float nx = -x * inv, ny = -y * inv, nz = -z * inv;

    float mono[20];
    mono[0]  = 1.0f;
    mono[1]  = nz;
    mono[2]  = nz * nz;
    mono[3]  = mono[2] * nz;
    mono[4]  = ny;
    mono[5]  = ny * nz;
    mono[6]  = ny * mono[2];
    mono[7]  = ny * ny;
    mono[8]  = mono[7] * nz;
    mono[9]  = mono[7] * ny;
    mono[10] = nx;
    mono[11] = nx * nz;
    mono[12] = nx * mono[2];
    mono[13] = nx * ny;
    mono[14] = mono[13] * nz;
    mono[15] = nx * mono[7];
    mono[16] = nx * nx;
    mono[17] = mono[16] * nz;
    mono[18] = mono[16] * ny;
    mono[19] = mono[16] * nx;

    #pragma unroll
    for (int m = 0; m < 16; m++) {
        float a = sY[m * 20];                 // mono[0] == 1
        #pragma unroll
        for (int t = 1; t < 20; t++)
            a = fmaf(sY[m * 20 + t], mono[t], a);
        sh[m] = a;
    }

    float e[4];
    float ssum = 0.0f;
    #pragma unroll
    for (int s = 0; s < 4; s++) {
        float d = dist - (float)s * (1.0f / 3.0f);
        e[s] = __expf(-16.0f * d * d);
        ssum += e[s];
    }
    float w = 1.0f / fmaxf(ssum, 1e-6f);
    if (dist > 1.0f) w = 0.0f;                // mask AFTER normalization (ref order)
    #pragma unroll
    for (int s = 0; s < 4; s++) shn[s] = e[s] * w;
}

// ---------------------------------------------------------------------------
__global__ void k_zero() {
    g_acc[threadIdx.x] = 0.0f;                // 128 threads
}

// One warp per v (32 lanes = 32 points). 8 warps/block, 2048 blocks.
// b = blockIdx.x >> 8   (256 blocks per batch, batch-aligned)
__global__ __launch_bounds__(256) void k_reduce(const float* __restrict__ patches,
                                                const float* __restrict__ Y) {
    __shared__ float sY[320];
    __shared__ float bacc[16];
    int tid = threadIdx.x;
    if (tid < 16)  bacc[tid] = 0.0f;
    for (int i = tid; i < 320; i += 256) sY[i] = Y[i];
    __syncthreads();

    int warp = tid >> 5;
    int lane = tid & 31;
    int g    = blockIdx.x * 8 + warp;         // global v index 0..16383
    int pt   = g * 32 + lane;

    const float* p = patches + (size_t)pt * 3;
    float x = p[0], y = p[1], z = p[2];

    float sh[16], shn[4];
    point_eval(sY, x, y, z, sh, shn);

    float q[4];
    q[0] = sh[0] * sh[0];
    q[1] = fmaf(sh[1], sh[1], fmaf(sh[2], sh[2], sh[3] * sh[3]));
    q[2] = fmaf(sh[4], sh[4], fmaf(sh[5], sh[5],
           fmaf(sh[6], sh[6], fmaf(sh[7], sh[7], sh[8] * sh[8]))));
    q[3] = fmaf(sh[9],  sh[9],  fmaf(sh[10], sh[10],
           fmaf(sh[11], sh[11], fmaf(sh[12], sh[12],
           fmaf(sh[13], sh[13], fmaf(sh[14], sh[14], sh[15] * sh[15]))))));

    float c[16];
    #pragma unroll
    for (int l = 0; l < 4; l++) {
        #pragma unroll
        for (int s = 0; s < 4; s++)
            c[l * 4 + s] = q[l] * (shn[s] * shn[s]);
    }

    // warp butterfly: sum over the 32 points of this v
    #pragma unroll
    for (int off = 16; off > 0; off >>= 1) {
        #pragma unroll
        for (int i = 0; i < 16; i++)
            c[i] += __shfl_xor_sync(0xffffffffu, c[i], off);
    }

    if (lane == 0) {
        #pragma unroll
        for (int i = 0; i < 16; i++)
            atomicAdd(&bacc[i], sqrtf(c[i]));   // sqrt per v, BEFORE mean over v
    }
    __syncthreads();

    if (tid < 16) {
        int b = blockIdx.x >> 8;
        atomicAdd(&g_acc[b * 16 + tid], bacc[tid]);
    }
}

__global__ void k_finalize() {
    int t = threadIdx.x;                      // 128 threads
    float ml = g_acc[t] * (1.0f / 2048.0f);
    g_ninv[t] = 1.0f / fmaxf(ml, 1e-8f);
}

// One thread per point; 64 contiguous fp32 out per point, 16x float4 stores.
__global__ __launch_bounds__(256) void k_out(const float* __restrict__ patches,
                                             const float* __restrict__ Y,
                                             float* __restrict__ out) {
    __shared__ float sY[320];
    __shared__ float sninv[16];
    int tid = threadIdx.x;
    if (tid < 16) {
        int b = blockIdx.x >> 8;              // 256 blocks per batch, batch-aligned
        sninv[tid] = g_ninv[b * 16 + tid];
    }
    for (int i = tid; i < 320; i += 256) sY[i] = Y[i];
    __syncthreads();

    int pt = blockIdx.x * 256 + tid;

    const float* p = patches + (size_t)pt * 3;
    float x = p[0], y = p[1], z = p[2];

    float sh[16], shn[4];
    point_eval(sY, x, y, z, sh, shn);

    float gls[16];
    #pragma unroll
    for (int l = 0; l < 4; l++) {
        #pragma unroll
        for (int s = 0; s < 4; s++)
            gls[l * 4 + s] = shn[s] * sninv[l * 4 + s];
    }

    float4* o = (float4*)(out + (size_t)pt * 64);
    #pragma unroll
    for (int m = 0; m < 16; m++) {
        const int l = (m == 0) ? 0 : (m < 4) ? 1 : (m < 9) ? 2 : 3;
        float4 v;
        v.x = sh[m] * gls[l * 4 + 0];
        v.y = sh[m] * gls[l * 4 + 1];
        v.z = sh[m] * gls[l * 4 + 2];
        v.w = sh[m] * gls[l * 4 + 3];
        o[m] = v;
    }
}

// ---------------------------------------------------------------------------
extern "C" void kernel_launch(void* const* d_in, const int* in_sizes, int n_in,
                              void* d_out, int out_size) {
    const float* patches = (const float*)d_in[0];
    const float* Y       = (const float*)d_in[1];
    float*       out     = (float*)d_out;

    k_zero<<<1, 128>>>();
    k_reduce<<<2048, 256>>>(patches, Y);
    k_finalize<<<1, 128>>>();
    k_out<<<2048, 256>>>(patches, Y, out);
}